// round 8
// baseline (speedup 1.0000x reference)
#include <cuda_runtime.h>

// Grid constants (match reference)
#define N_PIX_HI 512
#define NV_HI    256
#define N_PIX_LO 128
#define NV_LO    64
#define OUT_ELEMS (NV_LO * N_PIX_LO * N_PIX_LO)   // 1,048,576

// Reciprocals (1/0.025f == 40.0f exactly; 1/3.125f == 0.32f ~1ulp).
#define INV_PIX_HI_F  40.0f
#define INV_DV_HI_F   0.32f
#define FOV_HALF_HI_F 6.3875f
#define VEL0_HI_F     -404.6875f

// Predicated reduction: single @q RED instruction, no branch.
// False predicate suppresses the access entirely (address may be anything).
__device__ __forceinline__ void red_add(float* a, float v, int p) {
    asm volatile("{\n\t"
                 ".reg .pred q;\n\t"
                 "setp.ne.s32 q, %2, 0;\n\t"
                 "@q red.global.add.f32 [%0], %1;\n\t"
                 "}"
                 :: "l"(a), "f"(v), "r"(p) : "memory");
}

__global__ void __launch_bounds__(256) splat_kernel(
        const float* __restrict__ ra,
        const float* __restrict__ dec,
        const float* __restrict__ vel,
        const float* __restrict__ flux,
        float* __restrict__ out,
        int n) {
    int i = blockIdx.x * blockDim.x + threadIdx.x;
    if (i >= n) return;

    float x = fmaf(ra[i],  INV_PIX_HI_F, FOV_HALF_HI_F * INV_PIX_HI_F);
    float y = fmaf(dec[i], INV_PIX_HI_F, FOV_HALF_HI_F * INV_PIX_HI_F);
    float v = fmaf(vel[i], INV_DV_HI_F, -VEL0_HI_F * INV_DV_HI_F);

    float xf = floorf(x), yf = floorf(y), vf = floorf(v);
    int ix0 = (int)xf, iy0 = (int)yf, iv0 = (int)vf;
    float fx = x - xf, fy = y - yf, fv = v - vf;

    // valid: 0 <= i0 < N-1  ==  (unsigned)i0 < N-1
    int valid = ((unsigned)ix0 < N_PIX_HI - 1) &
                ((unsigned)iy0 < N_PIX_HI - 1) &
                ((unsigned)iv0 < NV_HI - 1);

    // split flags: hi-res corner i0+1 lands in a different low-res cell
    int sx = (ix0 & 3) == 3;
    int sy = (iy0 & 3) == 3;
    int sv = (iv0 & 3) == 3;

    // merged lo-corner weights: if not split, hi-corner weight folds to 1.0
    float wx0 = sx ? (1.0f - fx) : 1.0f;
    float wy0 = sy ? (1.0f - fy) : 1.0f;
    float wv0 = sv ? (1.0f - fv) : 1.0f;

    float f = flux[i] * (1.0f / 64.0f);   // block-mean folded in

    int cx0 = ix0 >> 2, cy0 = iy0 >> 2, cv0 = iv0 >> 2;
    float* o = out + ((cv0 * N_PIX_LO + cy0) * N_PIX_LO + cx0);

    float a0 = f * wv0 * wy0;   // (v0,y0)
    float a1 = f * wv0 * fy;    // (v0,y1) - only if sy
    float a2 = f * fv  * wy0;   // (v1,y0) - only if sv
    float a3 = f * fv  * fy;    // (v1,y1) - only if sv&sy

    const int SY = N_PIX_LO;
    const int SV = N_PIX_LO * N_PIX_LO;

    red_add(o,               a0 * wx0, valid);
    red_add(o + 1,           a0 * fx,  valid & sx);
    red_add(o + SY,          a1 * wx0, valid & sy);
    red_add(o + SY + 1,      a1 * fx,  valid & sy & sx);
    red_add(o + SV,          a2 * wx0, valid & sv);
    red_add(o + SV + 1,      a2 * fx,  valid & sv & sx);
    red_add(o + SV + SY,     a3 * wx0, valid & sv & sy);
    red_add(o + SV + SY + 1, a3 * fx,  valid & sv & sy & sx);
}

extern "C" void kernel_launch(void* const* d_in, const int* in_sizes, int n_in,
                              void* d_out, int out_size) {
    const float* ra   = (const float*)d_in[0];
    const float* dec  = (const float*)d_in[1];
    const float* vel  = (const float*)d_in[2];
    const float* flux = (const float*)d_in[3];
    float* out = (float*)d_out;
    int n = in_sizes[0];

    // Zero the output via a memset node (graph-capturable, no kernel launch).
    cudaMemsetAsync(out, 0, OUT_ELEMS * sizeof(float));

    splat_kernel<<<(n + 255) / 256, 256>>>(ra, dec, vel, flux, out, n);
}

// round 9
// speedup vs baseline: 1.0857x; 1.0857x over previous
#include <cuda_runtime.h>

// Grid constants (match reference)
#define N_PIX_HI 512
#define NV_HI    256
#define N_PIX_LO 128
#define NV_LO    64
#define OUT_ELEMS (NV_LO * N_PIX_LO * N_PIX_LO)   // 1,048,576

#define INV_PIX_HI_F  40.0f     // 1/0.025 exactly
#define INV_DV_HI_F   0.32f     // 1/3.125 (~1ulp)
#define FOV_HALF_HI_F 6.3875f
#define VEL0_HI_F     -404.6875f

// Predicated scalar reduction (false predicate suppresses the access).
__device__ __forceinline__ void red_add(float* a, float v, int p) {
    asm volatile("{\n\t"
                 ".reg .pred q;\n\t"
                 "setp.ne.s32 q, %2, 0;\n\t"
                 "@q red.global.add.f32 [%0], %1;\n\t"
                 "}"
                 :: "l"(a), "f"(v), "r"(p) : "memory");
}

// Predicated vector reduction: one 16B-aligned sector RMW (sm_90+).
__device__ __forceinline__ void red_add_v4(float* a, float v0, float v1,
                                           float v2, float v3, int p) {
    asm volatile("{\n\t"
                 ".reg .pred q;\n\t"
                 "setp.ne.s32 q, %5, 0;\n\t"
                 "@q red.global.add.v4.f32 [%0], {%1, %2, %3, %4};\n\t"
                 "}"
                 :: "l"(a), "f"(v0), "f"(v1), "f"(v2), "f"(v3), "r"(p)
                 : "memory");
}

__global__ void __launch_bounds__(256) splat_kernel(
        const float* __restrict__ ra,
        const float* __restrict__ dec,
        const float* __restrict__ vel,
        const float* __restrict__ flux,
        float* __restrict__ out,
        int n) {
    int i = blockIdx.x * blockDim.x + threadIdx.x;
    if (i >= n) return;

    float x = (ra[i]  + FOV_HALF_HI_F) * INV_PIX_HI_F;
    float y = (dec[i] + FOV_HALF_HI_F) * INV_PIX_HI_F;
    float v = (vel[i] - VEL0_HI_F)     * INV_DV_HI_F;

    float xf = floorf(x), yf = floorf(y), vf = floorf(v);
    int ix0 = (int)xf, iy0 = (int)yf, iv0 = (int)vf;
    float fx = x - xf, fy = y - yf, fv = v - vf;

    int valid = ((unsigned)ix0 < N_PIX_HI - 1) &
                ((unsigned)iy0 < N_PIX_HI - 1) &
                ((unsigned)iv0 < NV_HI - 1);

    // split flags: hi-res corner i0+1 lands in a different low-res cell
    int sx = (ix0 & 3) == 3;
    int sy = (iy0 & 3) == 3;
    int sv = (iv0 & 3) == 3;

    // merged y/v lo-corner weights (fold hi-corner to 1.0 when not split)
    float wy0 = sy ? (1.0f - fy) : 1.0f;
    float wv0 = sv ? (1.0f - fv) : 1.0f;

    float f = flux[i] * (1.0f / 64.0f);   // block-mean folded in

    int cx0 = ix0 >> 2, cy0 = iy0 >> 2, cv0 = iv0 >> 2;

    // x pattern inside the aligned 4-cell quad. slots untouched get 0.0
    // (adding 0.0f is exact). Straddle (q==3 && sx) spills into next quad.
    int q = cx0 & 3;
    float t0 = sx ? (1.0f - fx) : 1.0f;   // lo-corner weight (merged)
    float t1 = sx ? fx : 0.0f;            // hi-corner weight (0 when merged)
    float u0 = (q == 0) ? t0 : 0.0f;
    float u1 = (q == 1) ? t0 : ((q == 0) ? t1 : 0.0f);
    float u2 = (q == 2) ? t0 : ((q == 1) ? t1 : 0.0f);
    float u3 = (q == 3) ? t0 : ((q == 2) ? t1 : 0.0f);
    int straddle = (q == 3) & sx;         // hi-corner in next quad

    // 16B-aligned quad base (row stride 128 floats -> quad never crosses row)
    float* oq = out + ((cv0 * N_PIX_LO + cy0) * N_PIX_LO + (cx0 & ~3));

    float a0 = f * wv0 * wy0;   // (v0,y0)
    float a1 = f * wv0 * fy;    // (v0,y1) - only if sy
    float a2 = f * fv  * wy0;   // (v1,y0) - only if sv
    float a3 = f * fv  * fy;    // (v1,y1) - only if sv&sy

    const int SY = N_PIX_LO;
    const int SV = N_PIX_LO * N_PIX_LO;

    red_add_v4(oq,           a0*u0, a0*u1, a0*u2, a0*u3, valid);
    red_add_v4(oq + SY,      a1*u0, a1*u1, a1*u2, a1*u3, valid & sy);
    red_add_v4(oq + SV,      a2*u0, a2*u1, a2*u2, a2*u3, valid & sv);
    red_add_v4(oq + SV + SY, a3*u0, a3*u1, a3*u2, a3*u3, valid & sv & sy);

    // straddle spill: hi x-corner in the next quad's slot 0 (rare, P=1/16)
    red_add(oq + 4,           a0 * t1, valid & straddle);
    red_add(oq + 4 + SY,      a1 * t1, valid & straddle & sy);
    red_add(oq + 4 + SV,      a2 * t1, valid & straddle & sv);
    red_add(oq + 4 + SV + SY, a3 * t1, valid & straddle & sv & sy);
}

extern "C" void kernel_launch(void* const* d_in, const int* in_sizes, int n_in,
                              void* d_out, int out_size) {
    const float* ra   = (const float*)d_in[0];
    const float* dec  = (const float*)d_in[1];
    const float* vel  = (const float*)d_in[2];
    const float* flux = (const float*)d_in[3];
    float* out = (float*)d_out;
    int n = in_sizes[0];

    cudaMemsetAsync(out, 0, OUT_ELEMS * sizeof(float));

    splat_kernel<<<(n + 255) / 256, 256>>>(ra, dec, vel, flux, out, n);
}